// round 11
// baseline (speedup 1.0000x reference)
#include <cuda_runtime.h>
#include <cuda_fp16.h>
#include <cstring>

#define BATCH 8
#define M 4096
#define NPTS 4096
#define NSLICES 4
#define SLICE (NPTS / NSLICES)               // 1024 gt points per block
#define ROWS_PB 32                           // rows per block (4 per warp)
#define RGROUPS (M / ROWS_PB)                // 128
#define NBLOCKS (BATCH * RGROUPS * NSLICES)  // 4096
#define NROWS (BATCH * M)                    // 32768

// f16-exact scale: round_to_f16(10*log2(e)) = 14.4296875.
// ex2 arg: 12 - C*d  =>  e = 2^12 * softmin weight; the 2^12 cancels in w/s.
#define C_F16 14.4296875f
// Bias folded into p2 so the fma-chain d^2 is provably >= 0.
#define D2_BIAS 2e-5f

__device__ float g_s[NROWS * NSLICES];   // per-(row, slice) sum of e
__device__ float g_w[NROWS * NSLICES];   // per-(row, slice) sum of e*d
__device__ float g_p2[64];

// Fully-fused body for TWO rows x TWO points: distance fma chains + sqrt +
// f16 pack + ex2 + accumulate, one asm block -> no compiler glue movs.
#define BODY2(P0, P1, QX0, QY0, QZ0, PP0, QX1, QY1, QZ1, PP1, S0, W0, S1, W1) \
    asm("{\n\t"                                                               \
        ".reg .f32 b0, b1, c0, c1, s0, s1, t0, t1;\n\t"                       \
        ".reg .b32 hd0, hd1, a0, a1, e0, e1;\n\t"                             \
        /* row A: d2 for both points */                                       \
        "add.f32 b0, %10, %6;\n\t"                                            \
        "add.f32 b1, %14, %6;\n\t"                                            \
        "fma.rn.f32 b0, %5, %9, b0;\n\t"                                      \
        "fma.rn.f32 b1, %5, %13, b1;\n\t"                                     \
        "fma.rn.f32 b0, %4, %8, b0;\n\t"                                      \
        "fma.rn.f32 b1, %4, %12, b1;\n\t"                                     \
        "fma.rn.f32 b0, %3, %7, b0;\n\t"                                      \
        "fma.rn.f32 b1, %3, %11, b1;\n\t"                                     \
        /* row B: d2 for both points */                                       \
        "add.f32 c0, %10, %18;\n\t"                                           \
        "add.f32 c1, %14, %18;\n\t"                                           \
        "fma.rn.f32 c0, %17, %9, c0;\n\t"                                     \
        "fma.rn.f32 c1, %17, %13, c1;\n\t"                                    \
        "fma.rn.f32 c0, %16, %8, c0;\n\t"                                     \
        "fma.rn.f32 c1, %16, %12, c1;\n\t"                                    \
        "fma.rn.f32 c0, %15, %7, c0;\n\t"                                     \
        "fma.rn.f32 c1, %15, %11, c1;\n\t"                                    \
        /* 4 independent sqrt chains */                                       \
        "sqrt.approx.f32 s0, b0;\n\t"                                         \
        "sqrt.approx.f32 s1, b1;\n\t"                                         \
        "sqrt.approx.f32 t0, c0;\n\t"                                         \
        "sqrt.approx.f32 t1, c1;\n\t"                                         \
        "cvt.rn.f16x2.f32 hd0, s1, s0;\n\t"                                   \
        "cvt.rn.f16x2.f32 hd1, t1, t0;\n\t"                                   \
        "fma.rn.f16x2 a0, hd0, %19, %20;\n\t"                                 \
        "fma.rn.f16x2 a1, hd1, %19, %20;\n\t"                                 \
        "ex2.approx.f16x2 e0, a0;\n\t"                                        \
        "ex2.approx.f16x2 e1, a1;\n\t"                                        \
        "add.rn.f16x2 %0, %0, e0;\n\t"                                        \
        "fma.rn.f16x2 %1, e0, hd0, %1;\n\t"                                   \
        "add.rn.f16x2 %2, %2, e1;\n\t"                                        \
        "fma.rn.f16x2 %21, e1, hd1, %21;\n\t"                                 \
        "}"                                                                   \
        : "+r"(S0), "+r"(W0), "+r"(S1)                                        \
        : "f"(QX0), "f"(QY0), "f"(QZ0), "f"(PP0),                             \
          "f"((P0).x), "f"((P0).y), "f"((P0).z), "f"((P0).w),                 \
          "f"((P1).x), "f"((P1).y), "f"((P1).z), "f"((P1).w),                 \
          "f"(QX1), "f"(QY1), "f"(QZ1), "f"(PP1),                             \
          "r"(hC), "r"(hB), "r"(W1)                                           \
        , "0"(S0))

// note: W1 passed as input+tied via separate mechanism is messy; use simpler
// variant below with 4 outputs.
#undef BODY2
#define BODY2(P0, P1, QX0, QY0, QZ0, PP0, QX1, QY1, QZ1, PP1, S0, W0, S1, W1) \
    asm("{\n\t"                                                               \
        ".reg .f32 b0, b1, c0, c1, s0, s1, t0, t1;\n\t"                       \
        ".reg .b32 hd0, hd1, a0, a1, e0, e1;\n\t"                             \
        "add.f32 b0, %11, %7;\n\t"                                            \
        "add.f32 b1, %15, %7;\n\t"                                            \
        "fma.rn.f32 b0, %6, %10, b0;\n\t"                                     \
        "fma.rn.f32 b1, %6, %14, b1;\n\t"                                     \
        "fma.rn.f32 b0, %5, %9, b0;\n\t"                                      \
        "fma.rn.f32 b1, %5, %13, b1;\n\t"                                     \
        "fma.rn.f32 b0, %4, %8, b0;\n\t"                                      \
        "fma.rn.f32 b1, %4, %12, b1;\n\t"                                     \
        "add.f32 c0, %11, %19;\n\t"                                           \
        "add.f32 c1, %15, %19;\n\t"                                           \
        "fma.rn.f32 c0, %18, %10, c0;\n\t"                                    \
        "fma.rn.f32 c1, %18, %14, c1;\n\t"                                    \
        "fma.rn.f32 c0, %17, %9, c0;\n\t"                                     \
        "fma.rn.f32 c1, %17, %13, c1;\n\t"                                    \
        "fma.rn.f32 c0, %16, %8, c0;\n\t"                                     \
        "fma.rn.f32 c1, %16, %12, c1;\n\t"                                    \
        "sqrt.approx.f32 s0, b0;\n\t"                                         \
        "sqrt.approx.f32 s1, b1;\n\t"                                         \
        "sqrt.approx.f32 t0, c0;\n\t"                                         \
        "sqrt.approx.f32 t1, c1;\n\t"                                         \
        "cvt.rn.f16x2.f32 hd0, s1, s0;\n\t"                                   \
        "cvt.rn.f16x2.f32 hd1, t1, t0;\n\t"                                   \
        "fma.rn.f16x2 a0, hd0, %20, %21;\n\t"                                 \
        "fma.rn.f16x2 a1, hd1, %20, %21;\n\t"                                 \
        "ex2.approx.f16x2 e0, a0;\n\t"                                        \
        "ex2.approx.f16x2 e1, a1;\n\t"                                        \
        "add.rn.f16x2 %0, %0, e0;\n\t"                                        \
        "fma.rn.f16x2 %1, e0, hd0, %1;\n\t"                                   \
        "add.rn.f16x2 %2, %2, e1;\n\t"                                        \
        "fma.rn.f16x2 %3, e1, hd1, %3;\n\t"                                   \
        "}"                                                                   \
        : "+r"(S0), "+r"(W0), "+r"(S1), "+r"(W1)                              \
        : "f"(QX0), "f"(QY0), "f"(QZ0), "f"(PP0),                             \
          "f"((P0).x), "f"((P0).y), "f"((P0).z), "f"((P0).w),                 \
          "f"((P1).x), "f"((P1).y), "f"((P1).z), "f"((P1).w),                 \
          "f"(QX1), "f"(QY1), "f"(QZ1), "f"(PP1),                             \
          "r"(hC), "r"(hB))

__device__ __forceinline__ void flush_h2(unsigned& h, float& f) {
    __half2 v; memcpy(&v, &h, 4);
    f += __low2float(v) + __high2float(v);
    h = 0u;
}

__global__ __launch_bounds__(256, 4)
void emd_main(const float* __restrict__ pred, const float* __restrict__ gt)
{
    // AoS: one float4 {x, y, z, |g|^2} per gt point
    __shared__ __align__(16) float4 sPt[SLICE];

    const int bid = blockIdx.x;
    const int sl  = bid & (NSLICES - 1);
    const int rg  = (bid >> 2) & (RGROUPS - 1);
    const int b   = bid >> 9;

    // Stage slice coalesced: thread t owns points 4t..4t+3 via 3x float4
    {
        const float4* g4 = (const float4*)(gt + ((size_t)b * NPTS + (size_t)sl * SLICE) * 3);
        const int t = threadIdx.x;
        const float4 v0 = g4[3 * t + 0];
        const float4 v1 = g4[3 * t + 1];
        const float4 v2 = g4[3 * t + 2];
        float px[4], py[4], pz[4];
        px[0] = v0.x; py[0] = v0.y; pz[0] = v0.z;
        px[1] = v0.w; py[1] = v1.x; pz[1] = v1.y;
        px[2] = v1.z; py[2] = v1.w; pz[2] = v2.x;
        px[3] = v2.y; py[3] = v2.z; pz[3] = v2.w;
#pragma unroll
        for (int k = 0; k < 4; k++) {
            float g2 = fmaf(px[k], px[k], fmaf(py[k], py[k], pz[k] * pz[k]));
            sPt[4 * t + k] = make_float4(px[k], py[k], pz[k], g2);
        }
    }
    __syncthreads();

    const int warp = threadIdx.x >> 5;
    const int lane = threadIdx.x & 31;
    const int m0   = rg * ROWS_PB + warp * 4;   // this warp's 4 rows

    // Per-row scalar constants: q = -2p, p2 = |p|^2 + bias
    float qx[4], qy[4], qz[4], p2[4];
    const float* p = pred + ((size_t)b * M + m0) * 3;
#pragma unroll
    for (int r = 0; r < 4; r++) {
        float px = __ldg(p + 3 * r + 0);
        float py = __ldg(p + 3 * r + 1);
        float pz = __ldg(p + 3 * r + 2);
        qx[r] = -2.0f * px;
        qy[r] = -2.0f * py;
        qz[r] = -2.0f * pz;
        p2[r] = fmaf(px, px, fmaf(py, py, pz * pz)) + D2_BIAS;
    }

    unsigned hC, hB;
    { __half2 t = __float2half2_rn(-C_F16); memcpy(&hC, &t, 4); }
    { __half2 t = __float2half2_rn(12.0f);  memcpy(&hB, &t, 4); }

    unsigned sh[4] = {0u, 0u, 0u, 0u};
    unsigned wh[4] = {0u, 0u, 0u, 0u};
    float sF[4] = {0.f, 0.f, 0.f, 0.f};
    float wF[4] = {0.f, 0.f, 0.f, 0.f};

    // Conflict-free: lane L handles points {L+64j, L+32+64j}; two fused asm
    // bodies per j cover 4 rows x 2 points with zero compiler glue.
#pragma unroll
    for (int j = 0; j < 16; j++) {
        const int n = lane + 64 * j;
        const float4 P0 = sPt[n];
        const float4 P1 = sPt[n + 32];
        BODY2(P0, P1, qx[0], qy[0], qz[0], p2[0],
                      qx[1], qy[1], qz[1], p2[1],
              sh[0], wh[0], sh[1], wh[1]);
        BODY2(P0, P1, qx[2], qy[2], qz[2], p2[2],
                      qx[3], qy[3], qz[3], p2[3],
              sh[2], wh[2], sh[3], wh[3]);
        if (j == 7) {                 // single mid flush: <=8 f16 terms/half
#pragma unroll
            for (int r = 0; r < 4; r++) {
                flush_h2(sh[r], sF[r]);
                flush_h2(wh[r], wF[r]);
            }
        }
    }
#pragma unroll
    for (int r = 0; r < 4; r++) {
        flush_h2(sh[r], sF[r]);
        flush_h2(wh[r], wF[r]);
    }

    // Warp-reduce (s, w) per row; this warp owns (row, slice)
#pragma unroll
    for (int r = 0; r < 4; r++) {
        float s = sF[r], w = wF[r];
#pragma unroll
        for (int o = 16; o; o >>= 1) {
            s += __shfl_xor_sync(0xffffffffu, s, o);
            w += __shfl_xor_sync(0xffffffffu, w, o);
        }
        if (lane == 0) {
            const int row = b * M + m0 + r;
            g_s[row * NSLICES + sl] = s;
            g_w[row * NSLICES + sl] = w;
        }
    }
}

__global__ void emd_combine(void)
{
    __shared__ float sm[16];
    const int row = blockIdx.x * 512 + threadIdx.x;   // 64 x 512 = 32768 rows
    float s = 0.0f, w = 0.0f;
#pragma unroll
    for (int k = 0; k < NSLICES; k++) {
        s += g_s[row * NSLICES + k];
        w += g_w[row * NSLICES + k];
    }
    float val = w / s;                    // per-row softmin-weighted distance
#pragma unroll
    for (int o = 16; o; o >>= 1)
        val += __shfl_xor_sync(0xffffffffu, val, o);
    if ((threadIdx.x & 31) == 0) sm[threadIdx.x >> 5] = val;
    __syncthreads();
    if (threadIdx.x < 16) {
        float v = sm[threadIdx.x];
#pragma unroll
        for (int o = 8; o; o >>= 1)
            v += __shfl_xor_sync(0xffffu, v, o);
        if (threadIdx.x == 0) g_p2[blockIdx.x] = v;
    }
}

__global__ void emd_final(float* __restrict__ out)
{
    __shared__ float sm[2];
    float v = g_p2[threadIdx.x];          // 64 threads
#pragma unroll
    for (int o = 16; o; o >>= 1)
        v += __shfl_xor_sync(0xffffffffu, v, o);
    if ((threadIdx.x & 31) == 0) sm[threadIdx.x >> 5] = v;
    __syncthreads();
    if (threadIdx.x == 0)
        out[0] = (sm[0] + sm[1]) * (1.0f / (float)NROWS);   // LOSS_WEIGHT = 1.0
}

extern "C" void kernel_launch(void* const* d_in, const int* in_sizes, int n_in,
                              void* d_out, int out_size)
{
    const float* pred = (const float*)d_in[0];  // [B, M, 3] fp32
    const float* gt   = (const float*)d_in[1];  // [B, N, 3] fp32
    float* out        = (float*)d_out;          // scalar fp32

    emd_main<<<NBLOCKS, 256>>>(pred, gt);
    emd_combine<<<64, 512>>>();
    emd_final<<<1, 64>>>(out);
}